// round 6
// baseline (speedup 1.0000x reference)
#include <cuda_runtime.h>
#include <cstdint>

// ---------------------------------------------------------------------------
// CrossWarpingModule: B=2, C=64, H=W=256 -> 4 parity sub-images of 128x128,
// 8-head axial attention (per-head channel dim = 1), flow, bilinear warp.
//
//   K1  k_qkv  : 1x1 convs -> Q, K, V. 2-way channel-split reduction
//                (131072 threads) + smem combine for latency hiding.
//   K2  k_attn : MOMENT-BASED axial softmax (exp(qk) = sum q^n/n! k^n ->
//                29 per-line moments + deg-14 Horner per query), with
//                in-kernel transpose for the vertical direction.
//   K3  k_warp : bilinear border grid-sample + parity re-interleave,
//                8-channel gather batches for deep MLP.
// ---------------------------------------------------------------------------

#define PLANE 16384  // 128*128
typedef unsigned long long u64;
typedef unsigned int u32;

__device__ float g_Q [8][8][PLANE];
__device__ float g_K [8][8][PLANE];
__device__ float g_V [8][8][PLANE];
__device__ float g_flow[2][8][PLANE];  // dir0 = horizontal, dir1 = vertical

// ------------------------- packed f32x2 helpers ----------------------------
__device__ __forceinline__ u64 pk2f(float lo, float hi) {
    u64 r; asm("mov.b64 %0,{%1,%2};" : "=l"(r) : "f"(lo), "f"(hi)); return r;
}
__device__ __forceinline__ void upk2f(u64 v, float& lo, float& hi) {
    asm("mov.b64 {%0,%1},%2;" : "=f"(lo), "=f"(hi) : "l"(v));
}
__device__ __forceinline__ u64 fma2(u64 a, u64 b, u64 c) {
    u64 d; asm("fma.rn.f32x2 %0,%1,%2,%3;" : "=l"(d) : "l"(a), "l"(b), "l"(c)); return d;
}
__device__ __forceinline__ u64 add2(u64 a, u64 b) {
    u64 d; asm("add.rn.f32x2 %0,%1,%2;" : "=l"(d) : "l"(a), "l"(b)); return d;
}

// ---------------------------------------------------------------------------
// K1: QKV projections, channel-split 2-way.
// Block = 256 threads: halves t<128 / t>=128 each reduce 32 of the 64 input
// channels for 128 pixel-pairs; upper half dumps partials to smem, lower half
// combines and stores. 512 blocks -> 131072 threads.
// ---------------------------------------------------------------------------
__global__ __launch_bounds__(256) void k_qkv(
    const float* __restrict__ cur, const float* __restrict__ ref,
    const float* __restrict__ Wq, const float* __restrict__ Wk,
    const float* __restrict__ Wv)
{
    __shared__ u64 sW[3][512];
    __shared__ u64 sPart[128][24];
    int t = threadIdx.x;
    for (int i = t; i < 512; i += 256) {
        float wq = Wq[i];
        float wk = Wk[i];
        float wv = Wv[i];
        sW[0][i] = pk2f(wq, wq);
        sW[1][i] = pk2f(wk, wk);
        sW[2][i] = pk2f(wv, wv);
    }
    __syncthreads();

    int half = t >> 7;                    // which channel half
    int pl   = t & 127;                   // pixel-pair within block
    int idx  = blockIdx.x * 128 + pl;     // 65536 = 2(b) * 256(y) * 128(xpair)
    int b    = idx >> 15;
    int rem  = idx & 32767;
    int y    = rem >> 7;
    int xq   = rem & 127;
    int h2   = y >> 1, dyp = y & 1;

    u64 qa[8], ka[8], va[8];
#pragma unroll
    for (int h = 0; h < 8; ++h) { qa[h] = 0ull; ka[h] = 0ull; va[h] = 0ull; }

    int cbeg = half * 32;
    const float* curp = cur + ((size_t)b * 64 + cbeg) * 65536 + y * 256 + xq * 2;
    const float* refp = ref + ((size_t)b * 64 + cbeg) * 65536 + y * 256 + xq * 2;

#pragma unroll 4
    for (int c = 0; c < 32; ++c) {
        float2 cv = *(const float2*)(curp + (size_t)c * 65536);
        float2 rv = *(const float2*)(refp + (size_t)c * 65536);
        u64 c01 = pk2f(cv.x, cv.y);
        u64 r01 = pk2f(rv.x, rv.y);
        int cw = cbeg + c;
#pragma unroll
        for (int h = 0; h < 8; ++h) {
            qa[h] = fma2(sW[0][h * 64 + cw], c01, qa[h]);
            ka[h] = fma2(sW[1][h * 64 + cw], r01, ka[h]);
            va[h] = fma2(sW[2][h * 64 + cw], r01, va[h]);
        }
    }

    if (half) {
#pragma unroll
        for (int h = 0; h < 8; ++h) {
            sPart[pl][h]      = qa[h];
            sPart[pl][8 + h]  = ka[h];
            sPart[pl][16 + h] = va[h];
        }
    }
    __syncthreads();
    if (half) return;

    // parity sub mapping: (dy,dx) -> s : (0,0)->0 (1,1)->1 (0,1)->2 (1,0)->3
    int s0  = dyp ? 3 : 0;               // even-x pixel (lo lane)
    int s1  = dyp ? 1 : 2;               // odd-x pixel (hi lane)
    int sb0 = s0 * 2 + b, sb1 = s1 * 2 + b;
    int off = h2 * 128 + xq;
#pragma unroll
    for (int h = 0; h < 8; ++h) {
        float lo, hi;
        upk2f(add2(qa[h], sPart[pl][h]), lo, hi);
        g_Q[sb0][h][off] = lo; g_Q[sb1][h][off] = hi;
        upk2f(add2(ka[h], sPart[pl][8 + h]), lo, hi);
        g_K[sb0][h][off] = lo; g_K[sb1][h][off] = hi;
        upk2f(add2(va[h], sPart[pl][16 + h]), lo, hi);
        g_V[sb0][h][off] = lo; g_V[sb1][h][off] = hi;
    }
}

// ---------------------------------------------------------------------------
// K2: moment-based axial attention with in-kernel transpose for dir=1.
// Block = (dir, sb, 4 lines); 128 threads, warp per line.
// ---------------------------------------------------------------------------
#define NDEG 14

__global__ __launch_bounds__(128) void k_attn(
    const float* __restrict__ Wver, const float* __restrict__ Whor)
{
    __shared__ float sT[3][8][4][128];   // arr, head, line-in-block, pos (48KB)

    int t    = threadIdx.x;
    int wid  = t >> 5;
    int lane = t & 31;
    int bid  = blockIdx.x;               // 512 = 2 dir * 8 sb * 32 groups
    int dir  = bid >> 8;
    int sb   = (bid >> 5) & 7;
    int lg   = bid & 31;
    int c0   = lg * 4;                   // first line of this block

    const float* base_arr[3] = { &g_Q[sb][0][0], &g_K[sb][0][0], &g_V[sb][0][0] };

    // ---- stage into smem ----
    if (dir == 0) {
        int off = (c0 + wid) * 128 + lane * 4;
#pragma unroll
        for (int a = 0; a < 3; ++a)
#pragma unroll
            for (int h = 0; h < 8; ++h) {
                float4 v = *(const float4*)(base_arr[a] + h * PLANE + off);
                *(float4*)&sT[a][h][wid][lane * 4] = v;
            }
    } else {
        int off = t * 128 + c0;
#pragma unroll
        for (int a = 0; a < 3; ++a)
#pragma unroll
            for (int h = 0; h < 8; ++h) {
                float4 v = *(const float4*)(base_arr[a] + h * PLANE + off);
                sT[a][h][0][t] = v.x;
                sT[a][h][1][t] = v.y;
                sT[a][h][2][t] = v.z;
                sT[a][h][3][t] = v.w;
            }
    }
    __syncthreads();

    const float* wdp = dir ? Wver : Whor;

    const float invf[NDEG + 1] = {
        1.0f, 1.0f, 0.5f, 1.0f / 6.0f, 1.0f / 24.0f, 1.0f / 120.0f,
        1.0f / 720.0f, 1.0f / 5040.0f, 1.0f / 40320.0f, 1.0f / 362880.0f,
        1.0f / 3628800.0f, 1.0f / 39916800.0f, 1.0f / 479001600.0f,
        1.0f / 6227020800.0f, 1.0f / 87178291200.0f };

    float fl0 = 0.f, fl1 = 0.f, fl2 = 0.f, fl3 = 0.f;

#pragma unroll 1
    for (int head = 0; head < 8; ++head) {
        float wdh = wdp[head];
        float4 q4 = *(const float4*)&sT[0][head][wid][lane * 4];
        float4 k4 = *(const float4*)&sT[1][head][wid][lane * 4];
        float4 v4 = *(const float4*)&sT[2][head][wid][lane * 4];

        float m[NDEG + 1];
        float mv[NDEG + 1];
#pragma unroll
        for (int n = 0; n <= NDEG; ++n) { m[n] = 0.f; mv[n] = 0.f; }

        {
            float kk, vv, tt;
#define ACCUM(KX, VX)                                        \
            kk = (KX); vv = (VX); tt = kk;                   \
            mv[0] += vv;                                     \
            _Pragma("unroll")                                \
            for (int n = 1; n <= NDEG; ++n) {                \
                m[n] += tt;                                  \
                mv[n] = fmaf(tt, vv, mv[n]);                 \
                tt *= kk;                                    \
            }
            ACCUM(k4.x, v4.x)
            ACCUM(k4.y, v4.y)
            ACCUM(k4.z, v4.z)
            ACCUM(k4.w, v4.w)
#undef ACCUM
        }

#pragma unroll
        for (int off = 16; off; off >>= 1) {
            mv[0] += __shfl_xor_sync(0xffffffffu, mv[0], off);
#pragma unroll
            for (int n = 1; n <= NDEG; ++n) {
                m[n]  += __shfl_xor_sync(0xffffffffu, m[n],  off);
                mv[n] += __shfl_xor_sync(0xffffffffu, mv[n], off);
            }
        }

        m[0] = 128.0f;
#pragma unroll
        for (int n = 2; n <= NDEG; ++n) {
            m[n]  *= invf[n];
            mv[n] *= invf[n];
        }

#define EVAL(QX, FL)                                          \
        {                                                     \
            float q = (QX);                                   \
            float den = m[NDEG], num = mv[NDEG];              \
            _Pragma("unroll")                                 \
            for (int n = NDEG - 1; n >= 0; --n) {             \
                den = fmaf(den, q, m[n]);                     \
                num = fmaf(num, q, mv[n]);                    \
            }                                                 \
            FL = fmaf(wdh, __fdividef(num, den), FL);         \
        }
        EVAL(q4.x, fl0)
        EVAL(q4.y, fl1)
        EVAL(q4.z, fl2)
        EVAL(q4.w, fl3)
#undef EVAL
    }

    int base = (c0 + wid) * 128 + lane * 4;
    *(float4*)&g_flow[dir][sb][base] = make_float4(fl0, fl1, fl2, fl3);
}

// ---------------------------------------------------------------------------
// K3: bilinear border grid-sample + parity re-interleave.
// 4x channel-split; gathers batched 8 channels (32 loads in flight).
// ---------------------------------------------------------------------------
__global__ __launch_bounds__(256) void k_warp(
    const float* __restrict__ ref, float* __restrict__ out)
{
    int idx = blockIdx.x * 256 + threadIdx.x;   // 524288
    int pix = idx & 16383;
    int cid = (idx >> 14) & 3;                  // channel chunk 0..3
    int sb  = idx >> 16;                        // 0..7
    int h2  = pix >> 7, w2 = pix & 127;
    int s   = sb >> 1, b = sb & 1;
    int dy  = (s == 1 || s == 3) ? 1 : 0;
    int dx  = (s == 1 || s == 2) ? 1 : 0;

    float fx = g_flow[0][sb][(h2 << 7) + w2];
    float fy = g_flow[1][sb][(w2 << 7) + h2];
    float ix = (float)w2 + fx;
    float iy = (float)h2 + fy;
    float x0f = floorf(ix), y0f = floorf(iy);
    float wx = ix - x0f, wy = iy - y0f;
    int x0 = (int)x0f, y0 = (int)y0f;
    int x0c = min(max(x0, 0), 127), x1c = min(max(x0 + 1, 0), 127);
    int y0c = min(max(y0, 0), 127), y1c = min(max(y0 + 1, 0), 127);

    int X0 = 2 * x0c + dx, X1 = 2 * x1c + dx;
    int Y0 = 2 * y0c + dy, Y1 = 2 * y1c + dy;
    int o00 = Y0 * 256 + X0, o01 = Y0 * 256 + X1;
    int o10 = Y1 * 256 + X0, o11 = Y1 * 256 + X1;

    float w11 = wx * wy;
    float w01 = wx - w11;
    float w10 = wy - w11;
    float w00 = 1.f - wx - wy + w11;

    int c0 = cid * 16;
    const float* rp = ref + ((size_t)b * 64 + c0) * 65536;
    float*       op = out + ((size_t)b * 64 + c0) * 65536
                          + (2 * h2 + dy) * 256 + (2 * w2 + dx);

#pragma unroll
    for (int cc = 0; cc < 16; cc += 8) {
        float t00[8], t01[8], t10[8], t11[8];
#pragma unroll
        for (int c = 0; c < 8; ++c) {
            const float* p = rp + (size_t)(cc + c) * 65536;
            t00[c] = p[o00];
            t01[c] = p[o01];
            t10[c] = p[o10];
            t11[c] = p[o11];
        }
#pragma unroll
        for (int c = 0; c < 8; ++c) {
            float v = w00 * t00[c];
            v = fmaf(w01, t01[c], v);
            v = fmaf(w10, t10[c], v);
            v = fmaf(w11, t11[c], v);
            op[(size_t)(cc + c) * 65536] = v;
        }
    }
}

// ---------------------------------------------------------------------------
extern "C" void kernel_launch(void* const* d_in, const int* in_sizes, int n_in,
                              void* d_out, int out_size)
{
    const float* cur  = (const float*)d_in[0];
    const float* ref  = (const float*)d_in[1];
    const float* Wq   = (const float*)d_in[2];
    const float* Wk   = (const float*)d_in[3];
    const float* Wv   = (const float*)d_in[4];
    const float* Wver = (const float*)d_in[5];
    const float* Whor = (const float*)d_in[6];
    float* out = (float*)d_out;

    k_qkv<<<512, 256>>>(cur, ref, Wq, Wk, Wv);
    k_attn<<<512, 128>>>(Wver, Whor);
    k_warp<<<2048, 256>>>(ref, out);
}